// round 3
// baseline (speedup 1.0000x reference)
#include <cuda_runtime.h>
#include <cuda_bf16.h>
#include <math.h>

// Problem constants (fixed instance)
#define T_TOK   16384
#define C_DIM   1024
#define H_HEADS 16
#define HDIM    64
#define NSEG    32
#define SEGLEN  512

// Scratch (allocation-free: __device__ globals)
__device__ float g_qkv[(size_t)T_TOK * 3 * C_DIM];   // [T, 3C]
__device__ float g_y[(size_t)T_TOK * C_DIM];         // [T, C]

// ---------------------------------------------------------------------------
// Tiled fp32 GEMM: C[M,N] = A[M,K] * B[K,N], all row-major.
// 128x128 tile, BK=16, 256 threads, 8x8 per thread (4+4 split mapping).
// ---------------------------------------------------------------------------
__global__ __launch_bounds__(256, 2)
void sgemm128(const float* __restrict__ A, const float* __restrict__ B,
              float* __restrict__ C, int M, int N, int K)
{
    __shared__ float As[16][128];   // [k][m] (transposed)
    __shared__ float Bs[16][128];   // [k][n]

    const int tid = threadIdx.x;
    const int tx = tid & 15;        // 0..15 (n groups)
    const int ty = tid >> 4;        // 0..15 (m groups)
    const int bm = blockIdx.y * 128;
    const int bn = blockIdx.x * 128;

    const int arow = tid >> 2;            // 0..63
    const int acol = (tid & 3) << 2;      // 0,4,8,12
    const int brow = tid >> 5;            // 0..7
    const int bcol = (tid & 31) << 2;     // 0..124

    const float* Ap = A + (size_t)bm * K;
    const float* Bp = B + bn;

    float acc[8][8];
#pragma unroll
    for (int i = 0; i < 8; i++)
#pragma unroll
        for (int j = 0; j < 8; j++) acc[i][j] = 0.0f;

    for (int k0 = 0; k0 < K; k0 += 16) {
        float4 a0 = *(const float4*)(Ap + (size_t)(arow)      * K + k0 + acol);
        float4 a1 = *(const float4*)(Ap + (size_t)(arow + 64) * K + k0 + acol);
        float4 b0 = *(const float4*)(Bp + (size_t)(k0 + brow)     * N + bcol);
        float4 b1 = *(const float4*)(Bp + (size_t)(k0 + brow + 8) * N + bcol);

        __syncthreads();   // previous iteration's compute done reading smem
        As[acol + 0][arow] = a0.x; As[acol + 1][arow] = a0.y;
        As[acol + 2][arow] = a0.z; As[acol + 3][arow] = a0.w;
        As[acol + 0][arow + 64] = a1.x; As[acol + 1][arow + 64] = a1.y;
        As[acol + 2][arow + 64] = a1.z; As[acol + 3][arow + 64] = a1.w;
        *(float4*)&Bs[brow][bcol]     = b0;
        *(float4*)&Bs[brow + 8][bcol] = b1;
        __syncthreads();

#pragma unroll
        for (int kk = 0; kk < 16; kk++) {
            float ra[8], rb[8];
            *(float4*)&ra[0] = *(const float4*)&As[kk][ty * 4];
            *(float4*)&ra[4] = *(const float4*)&As[kk][64 + ty * 4];
            *(float4*)&rb[0] = *(const float4*)&Bs[kk][tx * 4];
            *(float4*)&rb[4] = *(const float4*)&Bs[kk][64 + tx * 4];
#pragma unroll
            for (int i = 0; i < 8; i++)
#pragma unroll
                for (int j = 0; j < 8; j++)
                    acc[i][j] += ra[i] * rb[j];
        }
    }

#pragma unroll
    for (int i = 0; i < 8; i++) {
        int row = bm + ((i < 4) ? (ty * 4 + i) : (64 + ty * 4 + (i - 4)));
        float4 v0 = make_float4(acc[i][0], acc[i][1], acc[i][2], acc[i][3]);
        float4 v1 = make_float4(acc[i][4], acc[i][5], acc[i][6], acc[i][7]);
        *(float4*)(C + (size_t)row * N + bn + tx * 4)      = v0;
        *(float4*)(C + (size_t)row * N + bn + 64 + tx * 4) = v1;
    }
}

// ---------------------------------------------------------------------------
// Fused block-diagonal attention, flash-style online softmax.
// Block: 256 threads, 64 queries of one (head, segment).
// smem: Qt [d][q] 16KB, KP (Kt [d][k] then P [q][k]) 16KB, Vs [k][d] 16KB.
// Each thread (tx,ty): S/P rows ty*4+i, cols tx*4+j; O rows ty*4+i, d cols tx*4+j.
// ---------------------------------------------------------------------------
__global__ __launch_bounds__(256)
void attn512(const float* __restrict__ qkv, float* __restrict__ y)
{
    __shared__ float Qt[64 * 64];
    __shared__ float KP[64 * 64];
    __shared__ float Vs[64 * 64];

    const int tid = threadIdx.x;
    const int tx = tid & 15;
    const int ty = tid >> 4;
    const int h   = blockIdx.x & (H_HEADS - 1);
    const int seg = blockIdx.x >> 4;
    const int q0  = seg * SEGLEN + blockIdx.y * 64;

    // --- Load Q tile transposed: Qt[d][q] ---
    {
        const int tok = tid >> 2;      // 0..63
        const int v0  = tid & 3;       // 0..3
        const float* qb = qkv + (size_t)q0 * (3 * C_DIM) + h * HDIM;
#pragma unroll
        for (int it = 0; it < 4; it++) {
            int dv = v0 + it * 4;      // float4 index along d
            float4 q4 = *(const float4*)(qb + (size_t)tok * (3 * C_DIM) + dv * 4);
            Qt[(dv * 4 + 0) * 64 + tok] = q4.x;
            Qt[(dv * 4 + 1) * 64 + tok] = q4.y;
            Qt[(dv * 4 + 2) * 64 + tok] = q4.z;
            Qt[(dv * 4 + 3) * 64 + tok] = q4.w;
        }
    }

    float O[4][4];
    float m[4], l[4];
#pragma unroll
    for (int i = 0; i < 4; i++) {
        m[i] = -1e30f; l[i] = 0.0f;
#pragma unroll
        for (int j = 0; j < 4; j++) O[i][j] = 0.0f;
    }

    for (int kc = 0; kc < SEGLEN; kc += 64) {
        const float* kb = qkv + (size_t)(seg * SEGLEN + kc) * (3 * C_DIM) + C_DIM + h * HDIM;
        const float* vb = kb + C_DIM;

        __syncthreads();   // previous iteration done reading KP/Vs (also covers Q STS)
        {
            const int tok = tid >> 2;
            const int v0  = tid & 3;
#pragma unroll
            for (int it = 0; it < 4; it++) {
                int dv = v0 + it * 4;
                float4 k4 = *(const float4*)(kb + (size_t)tok * (3 * C_DIM) + dv * 4);
                KP[(dv * 4 + 0) * 64 + tok] = k4.x;
                KP[(dv * 4 + 1) * 64 + tok] = k4.y;
                KP[(dv * 4 + 2) * 64 + tok] = k4.z;
                KP[(dv * 4 + 3) * 64 + tok] = k4.w;
                float4 v4 = *(const float4*)(vb + (size_t)tok * (3 * C_DIM) + dv * 4);
                *(float4*)&Vs[tok * 64 + dv * 4] = v4;
            }
        }
        __syncthreads();

        // --- S = Q * K^T (64x64 tile) ---
        float s[4][4];
#pragma unroll
        for (int i = 0; i < 4; i++)
#pragma unroll
            for (int j = 0; j < 4; j++) s[i][j] = 0.0f;

#pragma unroll 16
        for (int d = 0; d < 64; d++) {
            float4 qf = *(const float4*)&Qt[d * 64 + ty * 4];
            float4 kf = *(const float4*)&KP[d * 64 + tx * 4];
            s[0][0] += qf.x * kf.x; s[0][1] += qf.x * kf.y; s[0][2] += qf.x * kf.z; s[0][3] += qf.x * kf.w;
            s[1][0] += qf.y * kf.x; s[1][1] += qf.y * kf.y; s[1][2] += qf.y * kf.z; s[1][3] += qf.y * kf.w;
            s[2][0] += qf.z * kf.x; s[2][1] += qf.z * kf.y; s[2][2] += qf.z * kf.z; s[2][3] += qf.z * kf.w;
            s[3][0] += qf.w * kf.x; s[3][1] += qf.w * kf.y; s[3][2] += qf.w * kf.z; s[3][3] += qf.w * kf.w;
        }

        const float scale = 0.125f;   // 1/sqrt(64)
#pragma unroll
        for (int i = 0; i < 4; i++) {
#pragma unroll
            for (int j = 0; j < 4; j++) s[i][j] *= scale;

            float mc = fmaxf(fmaxf(s[i][0], s[i][1]), fmaxf(s[i][2], s[i][3]));
#pragma unroll
            for (int off = 1; off < 16; off <<= 1)
                mc = fmaxf(mc, __shfl_xor_sync(0xffffffffu, mc, off));

            float mn  = fmaxf(m[i], mc);
            float fac = __expf(m[i] - mn);
            float rs = 0.0f;
#pragma unroll
            for (int j = 0; j < 4; j++) {
                float p = __expf(s[i][j] - mn);
                s[i][j] = p;
                rs += p;
            }
#pragma unroll
            for (int off = 1; off < 16; off <<= 1)
                rs += __shfl_xor_sync(0xffffffffu, rs, off);

            l[i] = l[i] * fac + rs;
            m[i] = mn;
#pragma unroll
            for (int j = 0; j < 4; j++) O[i][j] *= fac;
        }

        __syncthreads();   // everyone done reading Kt before overwriting with P
#pragma unroll
        for (int i = 0; i < 4; i++)
            *(float4*)&KP[(ty * 4 + i) * 64 + tx * 4] =
                make_float4(s[i][0], s[i][1], s[i][2], s[i][3]);
        __syncthreads();

        // --- O += P * V ---
#pragma unroll 8
        for (int k = 0; k < 64; k += 4) {
            float4 pr[4], vr[4];
#pragma unroll
            for (int i = 0; i < 4; i++)
                pr[i] = *(const float4*)&KP[(ty * 4 + i) * 64 + k];
#pragma unroll
            for (int kk = 0; kk < 4; kk++)
                vr[kk] = *(const float4*)&Vs[(k + kk) * 64 + tx * 4];
#pragma unroll
            for (int i = 0; i < 4; i++) {
                O[i][0] += pr[i].x * vr[0].x + pr[i].y * vr[1].x + pr[i].z * vr[2].x + pr[i].w * vr[3].x;
                O[i][1] += pr[i].x * vr[0].y + pr[i].y * vr[1].y + pr[i].z * vr[2].y + pr[i].w * vr[3].y;
                O[i][2] += pr[i].x * vr[0].z + pr[i].y * vr[1].z + pr[i].z * vr[2].z + pr[i].w * vr[3].z;
                O[i][3] += pr[i].x * vr[0].w + pr[i].y * vr[1].w + pr[i].z * vr[2].w + pr[i].w * vr[3].w;
            }
        }
    }

    // --- Epilogue: normalize and write y in flat [T, C] layout ---
#pragma unroll
    for (int i = 0; i < 4; i++) {
        float inv = 1.0f / l[i];
        float4 o4 = make_float4(O[i][0] * inv, O[i][1] * inv, O[i][2] * inv, O[i][3] * inv);
        *(float4*)&y[(size_t)(q0 + ty * 4 + i) * C_DIM + h * HDIM + tx * 4] = o4;
    }
}

// ---------------------------------------------------------------------------
extern "C" void kernel_launch(void* const* d_in, const int* in_sizes, int n_in,
                              void* d_out, int out_size)
{
    const float* x      = (const float*)d_in[0];
    const float* w_attn = (const float*)d_in[1];
    const float* w_proj = (const float*)d_in[2];
    // d_in[3] = split_sections (int64) — segments are equal; constants baked in.
    float* out = (float*)d_out;

    void* qkv_p = nullptr;
    void* y_p   = nullptr;
    cudaGetSymbolAddress(&qkv_p, g_qkv);
    cudaGetSymbolAddress(&y_p,   g_y);
    float* qkv = (float*)qkv_p;
    float* y   = (float*)y_p;

    dim3 blk(256);

    // 1) qkv = x @ w_attn   [16384,1024] x [1024,3072]
    sgemm128<<<dim3(3 * C_DIM / 128, T_TOK / 128), blk>>>(x, w_attn, qkv,
                                                          T_TOK, 3 * C_DIM, C_DIM);
    // 2) block-diagonal attention -> y [T, C]
    attn512<<<dim3(H_HEADS * NSEG, SEGLEN / 64), blk>>>(qkv, y);

    // 3) out = y @ w_proj   [16384,1024] x [1024,1024]
    sgemm128<<<dim3(C_DIM / 128, T_TOK / 128), blk>>>(y, w_proj, out,
                                                      T_TOK, C_DIM, C_DIM);
}

// round 5
// speedup vs baseline: 1.6536x; 1.6536x over previous
#include <cuda_runtime.h>
#include <cuda_bf16.h>
#include <math.h>

// Problem constants (fixed instance)
#define T_TOK   16384
#define C_DIM   1024
#define H_HEADS 16
#define HDIM    64
#define NSEG    32
#define SEGLEN  512

// Scratch (allocation-free: __device__ globals)
__device__ float g_qkv[(size_t)T_TOK * 3 * C_DIM];   // [T, 3C]
__device__ float g_y[(size_t)T_TOK * C_DIM];         // [T, C]

// ---------------------------------------------------------------------------
// TF32 tensor-core GEMM: C[M,N] = A[M,K] * B[K,N], row-major.
// 128x128 block tile, BK=16, 256 threads = 8 warps (2 x 4), warp tile 64x32.
// mma.sync.aligned.m16n8k8.row.col.f32.tf32.tf32.f32
// Smem: k-pair-interleaved float2 fragments with xor swizzle -> conflict-free
// lds.64 fragment loads. Double buffered, 1 sync per K-tile.
// ---------------------------------------------------------------------------
__device__ __forceinline__ unsigned f2tf32(float x) {
    unsigned u;
    asm("cvt.rna.tf32.f32 %0, %1;" : "=r"(u) : "f"(x));
    return u;
}

#define KBPAD 516   // 128*4 float2 slots + 4 pad (shifts kb-region banks)

__global__ __launch_bounds__(256, 2)
void gemm_tf32(const float* __restrict__ A, const float* __restrict__ B,
               float* __restrict__ C, int M, int N, int K)
{
    __shared__ float2 As[2][2][KBPAD];   // [buf][kb][m*4 + swz(c)]
    __shared__ float2 Bs[2][2][KBPAD];   // [buf][kb][n*4 + swz(c)]

    const int tid  = threadIdx.x;
    const int lane = tid & 31;
    const int w    = tid >> 5;
    const int wm   = (w >> 2) * 64;      // warp M offset (0 or 64)
    const int wn   = (w & 3) * 32;       // warp N offset
    const int bm   = blockIdx.y * 128;
    const int bn   = blockIdx.x * 128;

    // A global->smem mapping: float4 rows (tid>>2, +64), k cols (tid&3)*4
    const int arow = tid >> 2;           // 0..63
    const int acol = (tid & 3) << 2;     // 0,4,8,12
    const int akb  = acol >> 3;          // k8-block
    const int ah   = (acol >> 2) & 1;    // pair half
    // B global->smem mapping: lanes vary k (16), groups of 8 n per thread
    const int bkk  = tid & 15;           // k within tile
    const int bng  = tid >> 4;           // 0..15 -> n group of 8
    const int bkb  = bkk >> 3;
    const int bp   = bkk & 3;
    const int bh   = (bkk >> 2) & 1;

    const float* Ap = A + (size_t)bm * K;
    const float* Bp = B + bn;

    float acc[4][4][4];
#pragma unroll
    for (int mt = 0; mt < 4; mt++)
#pragma unroll
        for (int nt = 0; nt < 4; nt++)
#pragma unroll
            for (int i = 0; i < 4; i++) acc[mt][nt][i] = 0.0f;

    const int fr = lane >> 2;   // fragment row-in-group 0..7
    const int fc = lane & 3;    // fragment col-in-group 0..3

    // Prefetch first tile
    float4 ra0 = *(const float4*)(Ap + (size_t)arow * K + acol);
    float4 ra1 = *(const float4*)(Ap + (size_t)(arow + 64) * K + acol);
    float4 rb0 = *(const float4*)(Bp + (size_t)bkk * N + bng * 8);
    float4 rb1 = *(const float4*)(Bp + (size_t)bkk * N + bng * 8 + 4);

    int cur = 0;
    for (int k0 = 0; k0 < K; k0 += 16) {
        // ---- store prefetched tile into smem[cur] (tf32-converted, swizzled) ----
        {
            float av0[4] = {ra0.x, ra0.y, ra0.z, ra0.w};
            float av1[4] = {ra1.x, ra1.y, ra1.z, ra1.w};
            float* a0p = (float*)&As[cur][akb][0];
#pragma unroll
            for (int e = 0; e < 4; e++) {
                int idx0 = (arow * 4 + (e ^ (arow & 3))) * 2 + ah;
                int idx1 = ((arow + 64) * 4 + (e ^ (arow & 3))) * 2 + ah;
                a0p[idx0] = __uint_as_float(f2tf32(av0[e]));
                a0p[idx1] = __uint_as_float(f2tf32(av1[e]));
            }
            float bv0[4] = {rb0.x, rb0.y, rb0.z, rb0.w};
            float bv1[4] = {rb1.x, rb1.y, rb1.z, rb1.w};
            float* b0p = (float*)&Bs[cur][bkb][0];
#pragma unroll
            for (int e = 0; e < 4; e++) {
                int n1 = bng * 8 + e;
                int n2 = bng * 8 + 4 + e;
                b0p[(n1 * 4 + (bp ^ e)) * 2 + bh] = __uint_as_float(f2tf32(bv0[e]));
                b0p[(n2 * 4 + (bp ^ e)) * 2 + bh] = __uint_as_float(f2tf32(bv1[e]));
            }
        }
        __syncthreads();

        // ---- prefetch next tile ----
        if (k0 + 16 < K) {
            ra0 = *(const float4*)(Ap + (size_t)arow * K + k0 + 16 + acol);
            ra1 = *(const float4*)(Ap + (size_t)(arow + 64) * K + k0 + 16 + acol);
            rb0 = *(const float4*)(Bp + (size_t)(k0 + 16 + bkk) * N + bng * 8);
            rb1 = *(const float4*)(Bp + (size_t)(k0 + 16 + bkk) * N + bng * 8 + 4);
        }

        // ---- compute on smem[cur]: 2 k8-steps x 16 mma per warp ----
#pragma unroll
        for (int kb = 0; kb < 2; kb++) {
            const float2* Ak = As[cur][kb];
            const float2* Bk = Bs[cur][kb];

            unsigned af[4][4];
#pragma unroll
            for (int mt = 0; mt < 4; mt++) {
                int row = wm + mt * 16 + fr;
                float2 lo = Ak[row * 4 + (fc ^ (row & 3))];
                float2 hi = Ak[(row + 8) * 4 + (fc ^ (row & 3))];
                af[mt][0] = __float_as_uint(lo.x);
                af[mt][1] = __float_as_uint(hi.x);
                af[mt][2] = __float_as_uint(lo.y);
                af[mt][3] = __float_as_uint(hi.y);
            }
            unsigned bf[4][2];
#pragma unroll
            for (int nt = 0; nt < 4; nt++) {
                int n = wn + nt * 8 + fr;
                float2 bb = Bk[n * 4 + (fc ^ (n & 3))];
                bf[nt][0] = __float_as_uint(bb.x);
                bf[nt][1] = __float_as_uint(bb.y);
            }
#pragma unroll
            for (int mt = 0; mt < 4; mt++)
#pragma unroll
                for (int nt = 0; nt < 4; nt++) {
                    asm volatile(
                        "mma.sync.aligned.m16n8k8.row.col.f32.tf32.tf32.f32 "
                        "{%0,%1,%2,%3}, {%4,%5,%6,%7}, {%8,%9}, {%0,%1,%2,%3};"
                        : "+f"(acc[mt][nt][0]), "+f"(acc[mt][nt][1]),
                          "+f"(acc[mt][nt][2]), "+f"(acc[mt][nt][3])
                        : "r"(af[mt][0]), "r"(af[mt][1]),
                          "r"(af[mt][2]), "r"(af[mt][3]),
                          "r"(bf[nt][0]), "r"(bf[nt][1]));
                }
        }
        cur ^= 1;
    }

    // ---- epilogue ----
#pragma unroll
    for (int mt = 0; mt < 4; mt++) {
#pragma unroll
        for (int nt = 0; nt < 4; nt++) {
            int row = bm + wm + mt * 16 + fr;
            int col = bn + wn + nt * 8 + 2 * fc;
            *(float2*)&C[(size_t)row * N + col] =
                make_float2(acc[mt][nt][0], acc[mt][nt][1]);
            *(float2*)&C[(size_t)(row + 8) * N + col] =
                make_float2(acc[mt][nt][2], acc[mt][nt][3]);
        }
    }
}

// ---------------------------------------------------------------------------
// Fused block-diagonal attention, flash-style online softmax (fp32, unchanged).
// ---------------------------------------------------------------------------
__global__ __launch_bounds__(256)
void attn512(const float* __restrict__ qkv, float* __restrict__ y)
{
    __shared__ float Qt[64 * 64];
    __shared__ float KP[64 * 64];
    __shared__ float Vs[64 * 64];

    const int tid = threadIdx.x;
    const int tx = tid & 15;
    const int ty = tid >> 4;
    const int h   = blockIdx.x & (H_HEADS - 1);
    const int seg = blockIdx.x >> 4;
    const int q0  = seg * SEGLEN + blockIdx.y * 64;

    {
        const int tok = tid >> 2;
        const int v0  = tid & 3;
        const float* qb = qkv + (size_t)q0 * (3 * C_DIM) + h * HDIM;
#pragma unroll
        for (int it = 0; it < 4; it++) {
            int dv = v0 + it * 4;
            float4 q4 = *(const float4*)(qb + (size_t)tok * (3 * C_DIM) + dv * 4);
            Qt[(dv * 4 + 0) * 64 + tok] = q4.x;
            Qt[(dv * 4 + 1) * 64 + tok] = q4.y;
            Qt[(dv * 4 + 2) * 64 + tok] = q4.z;
            Qt[(dv * 4 + 3) * 64 + tok] = q4.w;
        }
    }

    float O[4][4];
    float m[4], l[4];
#pragma unroll
    for (int i = 0; i < 4; i++) {
        m[i] = -1e30f; l[i] = 0.0f;
#pragma unroll
        for (int j = 0; j < 4; j++) O[i][j] = 0.0f;
    }

    for (int kc = 0; kc < SEGLEN; kc += 64) {
        const float* kb = qkv + (size_t)(seg * SEGLEN + kc) * (3 * C_DIM) + C_DIM + h * HDIM;
        const float* vb = kb + C_DIM;

        __syncthreads();
        {
            const int tok = tid >> 2;
            const int v0  = tid & 3;
#pragma unroll
            for (int it = 0; it < 4; it++) {
                int dv = v0 + it * 4;
                float4 k4 = *(const float4*)(kb + (size_t)tok * (3 * C_DIM) + dv * 4);
                KP[(dv * 4 + 0) * 64 + tok] = k4.x;
                KP[(dv * 4 + 1) * 64 + tok] = k4.y;
                KP[(dv * 4 + 2) * 64 + tok] = k4.z;
                KP[(dv * 4 + 3) * 64 + tok] = k4.w;
                float4 v4 = *(const float4*)(vb + (size_t)tok * (3 * C_DIM) + dv * 4);
                *(float4*)&Vs[tok * 64 + dv * 4] = v4;
            }
        }
        __syncthreads();

        float s[4][4];
#pragma unroll
        for (int i = 0; i < 4; i++)
#pragma unroll
            for (int j = 0; j < 4; j++) s[i][j] = 0.0f;

#pragma unroll 16
        for (int d = 0; d < 64; d++) {
            float4 qf = *(const float4*)&Qt[d * 64 + ty * 4];
            float4 kf = *(const float4*)&KP[d * 64 + tx * 4];
            s[0][0] += qf.x * kf.x; s[0][1] += qf.x * kf.y; s[0][2] += qf.x * kf.z; s[0][3] += qf.x * kf.w;
            s[1][0] += qf.y * kf.x; s[1][1] += qf.y * kf.y; s[1][2] += qf.y * kf.z; s[1][3] += qf.y * kf.w;
            s[2][0] += qf.z * kf.x; s[2][1] += qf.z * kf.y; s[2][2] += qf.z * kf.z; s[2][3] += qf.z * kf.w;
            s[3][0] += qf.w * kf.x; s[3][1] += qf.w * kf.y; s[3][2] += qf.w * kf.z; s[3][3] += qf.w * kf.w;
        }

        const float scale = 0.125f;
#pragma unroll
        for (int i = 0; i < 4; i++) {
#pragma unroll
            for (int j = 0; j < 4; j++) s[i][j] *= scale;

            float mc = fmaxf(fmaxf(s[i][0], s[i][1]), fmaxf(s[i][2], s[i][3]));
#pragma unroll
            for (int off = 1; off < 16; off <<= 1)
                mc = fmaxf(mc, __shfl_xor_sync(0xffffffffu, mc, off));

            float mn  = fmaxf(m[i], mc);
            float fac = __expf(m[i] - mn);
            float rs = 0.0f;
#pragma unroll
            for (int j = 0; j < 4; j++) {
                float p = __expf(s[i][j] - mn);
                s[i][j] = p;
                rs += p;
            }
#pragma unroll
            for (int off = 1; off < 16; off <<= 1)
                rs += __shfl_xor_sync(0xffffffffu, rs, off);

            l[i] = l[i] * fac + rs;
            m[i] = mn;
#pragma unroll
            for (int j = 0; j < 4; j++) O[i][j] *= fac;
        }

        __syncthreads();
#pragma unroll
        for (int i = 0; i < 4; i++)
            *(float4*)&KP[(ty * 4 + i) * 64 + tx * 4] =
                make_float4(s[i][0], s[i][1], s[i][2], s[i][3]);
        __syncthreads();

#pragma unroll 8
        for (int k = 0; k < 64; k += 4) {
            float4 pr[4], vr[4];
#pragma unroll
            for (int i = 0; i < 4; i++)
                pr[i] = *(const float4*)&KP[(ty * 4 + i) * 64 + k];
#pragma unroll
            for (int kk = 0; kk < 4; kk++)
                vr[kk] = *(const float4*)&Vs[(k + kk) * 64 + tx * 4];
#pragma unroll
            for (int i = 0; i < 4; i++) {
                O[i][0] += pr[i].x * vr[0].x + pr[i].y * vr[1].x + pr[i].z * vr[2].x + pr[i].w * vr[3].x;
                O[i][1] += pr[i].x * vr[0].y + pr[i].y * vr[1].y + pr[i].z * vr[2].y + pr[i].w * vr[3].y;
                O[i][2] += pr[i].x * vr[0].z + pr[i].y * vr[1].z + pr[i].z * vr[2].z + pr[i].w * vr[3].z;
                O[i][3] += pr[i].x * vr[0].w + pr[i].y * vr[1].w + pr[i].z * vr[2].w + pr[i].w * vr[3].w;
            }
        }
    }

#pragma unroll
    for (int i = 0; i < 4; i++) {
        float inv = 1.0f / l[i];
        float4 o4 = make_float4(O[i][0] * inv, O[i][1] * inv, O[i][2] * inv, O[i][3] * inv);
        *(float4*)&y[(size_t)(q0 + ty * 4 + i) * C_DIM + h * HDIM + tx * 4] = o4;
    }
}

// ---------------------------------------------------------------------------
extern "C" void kernel_launch(void* const* d_in, const int* in_sizes, int n_in,
                              void* d_out, int out_size)
{
    const float* x      = (const float*)d_in[0];
    const float* w_attn = (const float*)d_in[1];
    const float* w_proj = (const float*)d_in[2];
    float* out = (float*)d_out;

    void* qkv_p = nullptr;
    void* y_p   = nullptr;
    cudaGetSymbolAddress(&qkv_p, g_qkv);
    cudaGetSymbolAddress(&y_p,   g_y);
    float* qkv = (float*)qkv_p;
    float* y   = (float*)y_p;

    dim3 blk(256);

    // 1) qkv = x @ w_attn   [16384,1024] x [1024,3072]  (tf32 tensor cores)
    gemm_tf32<<<dim3(3 * C_DIM / 128, T_TOK / 128), blk>>>(x, w_attn, qkv,
                                                           T_TOK, 3 * C_DIM, C_DIM);
    // 2) block-diagonal attention -> y [T, C]
    attn512<<<dim3(H_HEADS * NSEG, SEGLEN / 64), blk>>>(qkv, y);

    // 3) out = y @ w_proj   [16384,1024] x [1024,1024]  (tf32 tensor cores)
    gemm_tf32<<<dim3(C_DIM / 128, T_TOK / 128), blk>>>(y, w_proj, out,
                                                       T_TOK, C_DIM, C_DIM);
}